// round 1
// baseline (speedup 1.0000x reference)
#include <cuda_runtime.h>

#define D       128
#define N_SRC   200000
#define N_MID   50000
#define N_DST   10000
#define E1      800000
#define E2      160000

// ---- scratch (static device globals; no runtime allocation allowed) ----
__device__ float g_agg1[N_MID * D];
__device__ float g_deg1[N_MID];
__device__ float g_h[N_MID * D];
__device__ float g_agg2[N_DST * D];
__device__ float g_deg2[N_DST];

// ---------------------------------------------------------------------
// Zero the accumulators (must run every call: atomics accumulate).
// ---------------------------------------------------------------------
__global__ void zero_kernel() {
    int tid = blockIdx.x * blockDim.x + threadIdx.x;
    int stride = gridDim.x * blockDim.x;
    float4 z = make_float4(0.f, 0.f, 0.f, 0.f);
    for (int i = tid; i < N_MID * D / 4; i += stride) ((float4*)g_agg1)[i] = z;
    for (int i = tid; i < N_DST * D / 4; i += stride) ((float4*)g_agg2)[i] = z;
    for (int i = tid; i < N_MID; i += stride) g_deg1[i] = 0.f;
    for (int i = tid; i < N_DST; i += stride) g_deg2[i] = 0.f;
}

// ---------------------------------------------------------------------
// Scatter-add: one warp per edge. Each lane moves 16B (float4) of the
// source row and reduces it into agg[col] with red.global.add.v4.f32
// (quarter the atomic-op count vs scalar atomicAdd). Lane 0 bumps degree.
// ---------------------------------------------------------------------
__global__ void scatter_kernel(const float* __restrict__ xsrc,
                               const int*   __restrict__ row,
                               const int*   __restrict__ col,
                               float*       __restrict__ agg,
                               float*       __restrict__ deg,
                               int E) {
    int warp_id = (blockIdx.x * blockDim.x + threadIdx.x) >> 5;
    int lane    = threadIdx.x & 31;
    if (warp_id >= E) return;
    int r = row[warp_id];
    int c = col[warp_id];

    float4 v = ((const float4*)(xsrc + (size_t)r * D))[lane];
    float* dst = agg + (size_t)c * D + lane * 4;
    asm volatile(
        "{ .reg .u64 p; cvta.to.global.u64 p, %0;\n\t"
        "  red.global.add.v4.f32 [p], {%1,%2,%3,%4}; }"
        :: "l"(dst), "f"(v.x), "f"(v.y), "f"(v.z), "f"(v.w) : "memory");

    if (lane == 0) atomicAdd(deg + c, 1.0f);
}

// ---------------------------------------------------------------------
// SAGE finish: mean = agg/deg (0 if deg==0), out = mean@Wl^T + b + xdst@Wr^T,
// L2-normalize, optional ReLU.
//
// Layout: 256 threads = 8 warps/block, 8 rows/warp (64 rows/block).
// Both weight matrices live in SMEM transposed (Wt[k][j], row stride 132
// to break the transpose-store bank conflict down to 8-way one-time cost).
// Inner loop per k: 1 LDS.128 (4 output cols of W) + 8 broadcast LDS
// (per-row input scalar) + 32 FFMA -> FMA-pipe bound, not LDS bound.
// ---------------------------------------------------------------------
#define KS 132                 // padded SMEM row stride for W^T
#define RPW 8                  // rows per warp
#define WARPS 8                // warps per block
#define ROWS_PER_BLOCK (RPW * WARPS)
#define SAGE_SMEM_BYTES ((2 * KS * D + D + WARPS * RPW * D) * 4)

template <bool RELU>
__global__ void __launch_bounds__(256, 1)
sage_kernel(const float* __restrict__ agg, const float* __restrict__ deg,
            const float* __restrict__ xdst,
            const float* __restrict__ Wl, const float* __restrict__ bl,
            const float* __restrict__ Wr,
            float* __restrict__ out, int n) {
    extern __shared__ float smem[];
    float* sWl = smem;                    // KS * 128
    float* sWr = smem + KS * D;           // KS * 128
    float* sb  = smem + 2 * KS * D;       // 128
    float* sIn = sb + D;                  // WARPS * RPW * 128 staging

    const int tid  = threadIdx.x;
    const int lane = tid & 31;
    const int warp = tid >> 5;
    const int l4   = lane * 4;

    // Cooperative transposed load of both weight matrices + bias
    for (int idx = tid; idx < D * D; idx += blockDim.x) {
        int j = idx >> 7;          // output column
        int k = idx & (D - 1);     // input dim
        sWl[k * KS + j] = Wl[idx];
        sWr[k * KS + j] = Wr[idx];
    }
    if (tid < D) sb[tid] = bl[tid];

    float* myIn = sIn + warp * (RPW * D);
    const int rowBase = blockIdx.x * ROWS_PER_BLOCK + warp * RPW;

    // ---- stage mean rows (agg * 1/deg) into warp-private SMEM ----
    #pragma unroll
    for (int r = 0; r < RPW; r++) {
        int row = rowBase + r;
        float4 v = make_float4(0.f, 0.f, 0.f, 0.f);
        if (row < n) {
            float dg   = deg[row];
            float invd = dg > 0.f ? 1.0f / dg : 0.f;
            v = ((const float4*)(agg + (size_t)row * D))[lane];
            v.x *= invd; v.y *= invd; v.z *= invd; v.w *= invd;
        }
        ((float4*)(myIn + r * D))[lane] = v;
    }
    __syncthreads();   // weights visible + staging ordered

    float acc[RPW][4];
    #pragma unroll
    for (int r = 0; r < RPW; r++) {
        acc[r][0] = acc[r][1] = acc[r][2] = acc[r][3] = 0.f;
    }

    // ---- phase A: mean @ Wl^T ----
    #pragma unroll 4
    for (int k = 0; k < D; k++) {
        float4 w = *(const float4*)&sWl[k * KS + l4];
        #pragma unroll
        for (int r = 0; r < RPW; r++) {
            float a = myIn[r * D + k];
            acc[r][0] += a * w.x;
            acc[r][1] += a * w.y;
            acc[r][2] += a * w.z;
            acc[r][3] += a * w.w;
        }
    }
    __syncwarp();

    // ---- stage xdst rows ----
    #pragma unroll
    for (int r = 0; r < RPW; r++) {
        int row = rowBase + r;
        float4 v = make_float4(0.f, 0.f, 0.f, 0.f);
        if (row < n) v = ((const float4*)(xdst + (size_t)row * D))[lane];
        ((float4*)(myIn + r * D))[lane] = v;
    }
    __syncwarp();

    // ---- phase B: + xdst @ Wr^T ----
    #pragma unroll 4
    for (int k = 0; k < D; k++) {
        float4 w = *(const float4*)&sWr[k * KS + l4];
        #pragma unroll
        for (int r = 0; r < RPW; r++) {
            float a = myIn[r * D + k];
            acc[r][0] += a * w.x;
            acc[r][1] += a * w.y;
            acc[r][2] += a * w.z;
            acc[r][3] += a * w.w;
        }
    }

    // ---- bias, L2-normalize, (ReLU), store ----
    float4 bv = *(const float4*)&sb[l4];
    #pragma unroll
    for (int r = 0; r < RPW; r++) {
        int row = rowBase + r;
        float o0 = acc[r][0] + bv.x;
        float o1 = acc[r][1] + bv.y;
        float o2 = acc[r][2] + bv.z;
        float o3 = acc[r][3] + bv.w;
        float s = o0 * o0 + o1 * o1 + o2 * o2 + o3 * o3;
        #pragma unroll
        for (int off = 16; off > 0; off >>= 1)
            s += __shfl_xor_sync(0xFFFFFFFFu, s, off);
        float inv = 1.0f / fmaxf(sqrtf(s), 1e-12f);
        o0 *= inv; o1 *= inv; o2 *= inv; o3 *= inv;
        if (RELU) {
            o0 = fmaxf(o0, 0.f); o1 = fmaxf(o1, 0.f);
            o2 = fmaxf(o2, 0.f); o3 = fmaxf(o3, 0.f);
        }
        if (row < n)
            ((float4*)(out + (size_t)row * D))[lane] = make_float4(o0, o1, o2, o3);
    }
}

// ---------------------------------------------------------------------
// Launch sequence (all default stream; graph-capturable, allocation-free)
// ---------------------------------------------------------------------
extern "C" void kernel_launch(void* const* d_in, const int* in_sizes, int n_in,
                              void* d_out, int out_size) {
    const float* x    = (const float*)d_in[0];
    const float* Wl1  = (const float*)d_in[1];
    const float* bl1  = (const float*)d_in[2];
    const float* Wr1  = (const float*)d_in[3];
    const float* Wl2  = (const float*)d_in[4];
    const float* bl2  = (const float*)d_in[5];
    const float* Wr2  = (const float*)d_in[6];
    const int*   row1 = (const int*)d_in[7];
    const int*   col1 = (const int*)d_in[8];
    const int*   row2 = (const int*)d_in[9];
    const int*   col2 = (const int*)d_in[10];
    float* out = (float*)d_out;

    float *agg1, *deg1, *h, *agg2, *deg2;
    cudaGetSymbolAddress((void**)&agg1, g_agg1);
    cudaGetSymbolAddress((void**)&deg1, g_deg1);
    cudaGetSymbolAddress((void**)&h,    g_h);
    cudaGetSymbolAddress((void**)&agg2, g_agg2);
    cudaGetSymbolAddress((void**)&deg2, g_deg2);

    cudaFuncSetAttribute(sage_kernel<true>,
                         cudaFuncAttributeMaxDynamicSharedMemorySize, SAGE_SMEM_BYTES);
    cudaFuncSetAttribute(sage_kernel<false>,
                         cudaFuncAttributeMaxDynamicSharedMemorySize, SAGE_SMEM_BYTES);

    zero_kernel<<<2048, 256>>>();

    // layer 1: scatter x over (row1 -> col1) into agg1/deg1
    {
        int blocks = (E1 * 32 + 255) / 256;
        scatter_kernel<<<blocks, 256>>>(x, row1, col1, agg1, deg1, E1);
    }
    // layer 1 finish: h = relu(normalize(mean@Wl1^T + b + x@Wr1^T))
    {
        int blocks = (N_MID + ROWS_PER_BLOCK - 1) / ROWS_PER_BLOCK;
        sage_kernel<true><<<blocks, 256, SAGE_SMEM_BYTES>>>(
            agg1, deg1, x, Wl1, bl1, Wr1, h, N_MID);
    }
    // layer 2: scatter h over (row2 -> col2) into agg2/deg2
    {
        int blocks = (E2 * 32 + 255) / 256;
        scatter_kernel<<<blocks, 256>>>(h, row2, col2, agg2, deg2, E2);
    }
    // layer 2 finish: out = normalize(mean@Wl2^T + b + h@Wr2^T)
    {
        int blocks = (N_DST + ROWS_PER_BLOCK - 1) / ROWS_PER_BLOCK;
        sage_kernel<false><<<blocks, 256, SAGE_SMEM_BYTES>>>(
            agg2, deg2, h, Wl2, bl2, Wr2, out, N_DST);
    }
}

// round 2
// speedup vs baseline: 1.1879x; 1.1879x over previous
#include <cuda_runtime.h>

#define D       128
#define N_SRC   200000
#define N_MID   50000
#define N_DST   10000
#define E1      800000
#define E2      160000

typedef unsigned long long u64t;

// ---- scratch (static device globals; no runtime allocation allowed) ----
__device__ int   g_cnt[N_MID];        // per-dst edge counts (reused layer 2)
__device__ int   g_cur[N_MID];        // placement cursors
__device__ int   g_off[N_MID + 1];    // CSR offsets
__device__ int   g_eidx[E1];          // src row per CSR-sorted edge
__device__ float g_agg[N_MID * D];    // mean-aggregated features
__device__ float g_h[N_MID * D];      // layer-1 output

// ---------------------------------------------------------------------
// CSR build step 1: zero counters + cursors
// ---------------------------------------------------------------------
__global__ void zero_cnt_kernel(int n) {
    int i = blockIdx.x * blockDim.x + threadIdx.x;
    if (i < n) { g_cnt[i] = 0; g_cur[i] = 0; }
}

// CSR build step 2: histogram of destination columns
__global__ void hist_kernel(const int* __restrict__ col, int E) {
    int i = blockIdx.x * blockDim.x + threadIdx.x;
    if (i < E) atomicAdd(&g_cnt[col[i]], 1);
}

// CSR build step 3: exclusive scan (single block, warp-shfl based)
__global__ void __launch_bounds__(1024, 1)
scan_kernel(int n) {
    __shared__ int wsum[32];
    __shared__ int carry_s;
    const int t = threadIdx.x, lane = t & 31, warp = t >> 5;
    if (t == 0) carry_s = 0;
    __syncthreads();
    for (int base = 0; base < n; base += 1024) {
        int idx = base + t;
        int v = (idx < n) ? g_cnt[idx] : 0;
        int x = v;
        #pragma unroll
        for (int d = 1; d < 32; d <<= 1) {
            int y = __shfl_up_sync(0xffffffffu, x, d);
            if (lane >= d) x += y;
        }
        if (lane == 31) wsum[warp] = x;
        __syncthreads();
        if (warp == 0) {
            int wv = wsum[lane];
            int wx = wv;
            #pragma unroll
            for (int d = 1; d < 32; d <<= 1) {
                int y = __shfl_up_sync(0xffffffffu, wx, d);
                if (lane >= d) wx += y;
            }
            wsum[lane] = wx - wv;           // exclusive warp offsets
        }
        __syncthreads();
        int incl = x + wsum[warp];
        int carry = carry_s;
        if (idx < n) g_off[idx] = carry + incl - v;
        __syncthreads();                    // everyone read carry_s
        if (t == 1023) carry_s = carry + incl;
        __syncthreads();
    }
    if (t == 0) g_off[n] = carry_s;
}

// CSR build step 4: place edge source-ids into buckets
__global__ void place_kernel(const int* __restrict__ row,
                             const int* __restrict__ col, int E) {
    int i = blockIdx.x * blockDim.x + threadIdx.x;
    if (i < E) {
        int c = col[i];
        int slot = g_off[c] + atomicAdd(&g_cur[c], 1);
        g_eidx[slot] = row[i];
    }
}

// ---------------------------------------------------------------------
// Aggregation: one warp per destination row; gather+sum its in-edges
// with plain LDG.128 (no atomics), write the mean.
// ---------------------------------------------------------------------
__global__ void agg_kernel(const float* __restrict__ xsrc,
                           float* __restrict__ agg, int n) {
    int c    = (blockIdx.x * blockDim.x + threadIdx.x) >> 5;
    int lane = threadIdx.x & 31;
    if (c >= n) return;
    int s = g_off[c], e = g_off[c + 1];

    float4 acc = make_float4(0.f, 0.f, 0.f, 0.f);
    int i = s;
    for (; i + 4 <= e; i += 4) {            // MLP=4 independent gathers
        int r0 = g_eidx[i + 0];
        int r1 = g_eidx[i + 1];
        int r2 = g_eidx[i + 2];
        int r3 = g_eidx[i + 3];
        float4 v0 = ((const float4*)(xsrc + (size_t)r0 * D))[lane];
        float4 v1 = ((const float4*)(xsrc + (size_t)r1 * D))[lane];
        float4 v2 = ((const float4*)(xsrc + (size_t)r2 * D))[lane];
        float4 v3 = ((const float4*)(xsrc + (size_t)r3 * D))[lane];
        acc.x += (v0.x + v1.x) + (v2.x + v3.x);
        acc.y += (v0.y + v1.y) + (v2.y + v3.y);
        acc.z += (v0.z + v1.z) + (v2.z + v3.z);
        acc.w += (v0.w + v1.w) + (v2.w + v3.w);
    }
    for (; i < e; i++) {
        int r = g_eidx[i];
        float4 v = ((const float4*)(xsrc + (size_t)r * D))[lane];
        acc.x += v.x; acc.y += v.y; acc.z += v.z; acc.w += v.w;
    }
    float invd = (e > s) ? 1.0f / (float)(e - s) : 0.f;
    acc.x *= invd; acc.y *= invd; acc.z *= invd; acc.w *= invd;
    ((float4*)(agg + (size_t)c * D))[lane] = acc;
}

// ---------------------------------------------------------------------
// SAGE finish: out = mean@Wl^T + b + xdst@Wr^T, L2-normalize, opt ReLU.
// Inner loops use Blackwell packed f32x2 FMA (2x FP32 FMA rate, exact).
// ---------------------------------------------------------------------
#define KS 132
#define RPW 8
#define WARPS 8
#define ROWS_PER_BLOCK (RPW * WARPS)
#define SAGE_SMEM_BYTES ((2 * KS * D + D + WARPS * RPW * D) * 4)

__device__ __forceinline__ u64t pack2(float a) {
    u64t r;
    unsigned ai = __float_as_uint(a);
    asm("mov.b64 %0, {%1, %1};" : "=l"(r) : "r"(ai));
    return r;
}
__device__ __forceinline__ void ffma2(u64t& d, u64t a, u64t b) {
    asm("fma.rn.f32x2 %0, %1, %2, %3;" : "=l"(d) : "l"(a), "l"(b), "l"(d));
}

template <bool RELU>
__global__ void __launch_bounds__(256, 1)
sage_kernel(const float* __restrict__ agg,
            const float* __restrict__ xdst,
            const float* __restrict__ Wl, const float* __restrict__ bl,
            const float* __restrict__ Wr,
            float* __restrict__ out, int n) {
    extern __shared__ float smem[];
    float* sWl = smem;                    // KS * 128 (transposed)
    float* sWr = smem + KS * D;           // KS * 128 (transposed)
    float* sb  = smem + 2 * KS * D;       // 128
    float* sIn = sb + D;                  // WARPS * RPW * 128 staging

    const int tid  = threadIdx.x;
    const int lane = tid & 31;
    const int warp = tid >> 5;
    const int l4   = lane * 4;

    for (int idx = tid; idx < D * D; idx += blockDim.x) {
        int j = idx >> 7;
        int k = idx & (D - 1);
        sWl[k * KS + j] = Wl[idx];
        sWr[k * KS + j] = Wr[idx];
    }
    if (tid < D) sb[tid] = bl[tid];

    float* myIn = sIn + warp * (RPW * D);
    const int rowBase = blockIdx.x * ROWS_PER_BLOCK + warp * RPW;

    // ---- stage mean rows ----
    #pragma unroll
    for (int r = 0; r < RPW; r++) {
        int row = rowBase + r;
        float4 v = make_float4(0.f, 0.f, 0.f, 0.f);
        if (row < n) v = ((const float4*)(agg + (size_t)row * D))[lane];
        ((float4*)(myIn + r * D))[lane] = v;
    }
    __syncthreads();

    u64t acc[RPW][2];
    {
        u64t b0 = *(const u64t*)&sb[l4];
        u64t b1 = *(const u64t*)&sb[l4 + 2];
        #pragma unroll
        for (int r = 0; r < RPW; r++) { acc[r][0] = b0; acc[r][1] = b1; }
    }

    // ---- phase A: mean @ Wl^T ----
    #pragma unroll 4
    for (int k = 0; k < D; k++) {
        ulonglong2 w = *(const ulonglong2*)&sWl[k * KS + l4];
        #pragma unroll
        for (int r = 0; r < RPW; r++) {
            u64t a = pack2(myIn[r * D + k]);
            ffma2(acc[r][0], a, w.x);
            ffma2(acc[r][1], a, w.y);
        }
    }
    __syncwarp();

    // ---- restage xdst rows ----
    #pragma unroll
    for (int r = 0; r < RPW; r++) {
        int row = rowBase + r;
        float4 v = make_float4(0.f, 0.f, 0.f, 0.f);
        if (row < n) v = ((const float4*)(xdst + (size_t)row * D))[lane];
        ((float4*)(myIn + r * D))[lane] = v;
    }
    __syncwarp();

    // ---- phase B: + xdst @ Wr^T ----
    #pragma unroll 4
    for (int k = 0; k < D; k++) {
        ulonglong2 w = *(const ulonglong2*)&sWr[k * KS + l4];
        #pragma unroll
        for (int r = 0; r < RPW; r++) {
            u64t a = pack2(myIn[r * D + k]);
            ffma2(acc[r][0], a, w.x);
            ffma2(acc[r][1], a, w.y);
        }
    }

    // ---- L2-normalize, (ReLU), store ----
    union F2 { u64t u; float2 f; };
    #pragma unroll
    for (int r = 0; r < RPW; r++) {
        int row = rowBase + r;
        F2 a0, a1; a0.u = acc[r][0]; a1.u = acc[r][1];
        float o0 = a0.f.x, o1 = a0.f.y, o2 = a1.f.x, o3 = a1.f.y;
        float s = o0 * o0 + o1 * o1 + o2 * o2 + o3 * o3;
        #pragma unroll
        for (int off = 16; off > 0; off >>= 1)
            s += __shfl_xor_sync(0xFFFFFFFFu, s, off);
        float inv = 1.0f / fmaxf(sqrtf(s), 1e-12f);
        o0 *= inv; o1 *= inv; o2 *= inv; o3 *= inv;
        if (RELU) {
            o0 = fmaxf(o0, 0.f); o1 = fmaxf(o1, 0.f);
            o2 = fmaxf(o2, 0.f); o3 = fmaxf(o3, 0.f);
        }
        if (row < n)
            ((float4*)(out + (size_t)row * D))[lane] = make_float4(o0, o1, o2, o3);
    }
}

// ---------------------------------------------------------------------
// Launch sequence (default stream; graph-capturable, allocation-free)
// ---------------------------------------------------------------------
extern "C" void kernel_launch(void* const* d_in, const int* in_sizes, int n_in,
                              void* d_out, int out_size) {
    const float* x    = (const float*)d_in[0];
    const float* Wl1  = (const float*)d_in[1];
    const float* bl1  = (const float*)d_in[2];
    const float* Wr1  = (const float*)d_in[3];
    const float* Wl2  = (const float*)d_in[4];
    const float* bl2  = (const float*)d_in[5];
    const float* Wr2  = (const float*)d_in[6];
    const int*   row1 = (const int*)d_in[7];
    const int*   col1 = (const int*)d_in[8];
    const int*   row2 = (const int*)d_in[9];
    const int*   col2 = (const int*)d_in[10];
    float* out = (float*)d_out;

    float *agg, *h;
    cudaGetSymbolAddress((void**)&agg, g_agg);
    cudaGetSymbolAddress((void**)&h,   g_h);

    cudaFuncSetAttribute(sage_kernel<true>,
                         cudaFuncAttributeMaxDynamicSharedMemorySize, SAGE_SMEM_BYTES);
    cudaFuncSetAttribute(sage_kernel<false>,
                         cudaFuncAttributeMaxDynamicSharedMemorySize, SAGE_SMEM_BYTES);

    // ======== layer 1 ========
    zero_cnt_kernel<<<(N_MID + 255) / 256, 256>>>(N_MID);
    hist_kernel<<<(E1 + 255) / 256, 256>>>(col1, E1);
    scan_kernel<<<1, 1024>>>(N_MID);
    place_kernel<<<(E1 + 255) / 256, 256>>>(row1, col1, E1);
    agg_kernel<<<(N_MID * 32 + 255) / 256, 256>>>(x, agg, N_MID);
    sage_kernel<true><<<(N_MID + ROWS_PER_BLOCK - 1) / ROWS_PER_BLOCK, 256,
                        SAGE_SMEM_BYTES>>>(agg, x, Wl1, bl1, Wr1, h, N_MID);

    // ======== layer 2 ========
    zero_cnt_kernel<<<(N_DST + 255) / 256, 256>>>(N_DST);
    hist_kernel<<<(E2 + 255) / 256, 256>>>(col2, E2);
    scan_kernel<<<1, 1024>>>(N_DST);
    place_kernel<<<(E2 + 255) / 256, 256>>>(row2, col2, E2);
    agg_kernel<<<(N_DST * 32 + 255) / 256, 256>>>(h, agg, N_DST);
    sage_kernel<false><<<(N_DST + ROWS_PER_BLOCK - 1) / ROWS_PER_BLOCK, 256,
                         SAGE_SMEM_BYTES>>>(agg, h, Wl2, bl2, Wr2, out, N_DST);
}

// round 3
// speedup vs baseline: 1.5538x; 1.3080x over previous
#include <cuda_runtime.h>

#define D       128
#define N_SRC   200000
#define N_MID   50000
#define N_DST   10000
#define E1      800000
#define E2      160000

typedef unsigned long long u64t;

#define SCAN_CHUNK 2048               // elements per scan block
#define NB1 ((N_MID + SCAN_CHUNK - 1) / SCAN_CHUNK)   // 25
#define NB2 ((N_DST + SCAN_CHUNK - 1) / SCAN_CHUNK)   // 5

// ---- scratch (static device globals; no runtime allocation) ----
__device__ int   g_cnt1[N_MID + SCAN_CHUNK];   // padded for unguarded int4 loads
__device__ int   g_off1[NB1 * SCAN_CHUNK];     // within-block exclusive prefixes
__device__ int   g_bsum1[32];                  // per-block totals -> exclusive
__device__ int   g_eidx1[E1];
__device__ int   g_slot1[E1];
__device__ int   g_cnt2[N_DST + SCAN_CHUNK];
__device__ int   g_off2[NB2 * SCAN_CHUNK];
__device__ int   g_bsum2[32];
__device__ int   g_eidx2[E2];
__device__ int   g_slot2[E2];
__device__ float g_agg[N_MID * D];
__device__ float g_h[N_MID * D];

// ---------------------------------------------------------------------
// Zero both (padded) count arrays in one launch.
// ---------------------------------------------------------------------
__global__ void zero_all(int* c1, int n1, int* c2, int n2) {
    int i = blockIdx.x * blockDim.x + threadIdx.x;
    if (i < n1) c1[i] = 0;
    if (i < n2) c2[i] = 0;
}

// Histogram + slot assignment in one pass (atomic return value = slot).
__global__ void hist_slot(const int* __restrict__ col,
                          int* __restrict__ cnt,
                          int* __restrict__ slot, int E) {
    int i = blockIdx.x * blockDim.x + threadIdx.x;
    if (i < E) slot[i] = atomicAdd(&cnt[col[i]], 1);
}

// Stage 1: per-block scan. Each block scans SCAN_CHUNK counts (256 thr x 8).
// Writes within-block EXCLUSIVE prefixes to off[] and block total to bsum[b].
__global__ void __launch_bounds__(256, 4)
scan_partial(const int* __restrict__ cnt, int* __restrict__ off,
             int* __restrict__ bsum) {
    __shared__ int wsum[8];
    const int t = threadIdx.x, lane = t & 31, w = t >> 5;
    const int base = blockIdx.x * SCAN_CHUNK + t * 8;

    int4 a = *(const int4*)(cnt + base);
    int4 b = *(const int4*)(cnt + base + 4);
    int v[8] = {a.x, a.y, a.z, a.w, b.x, b.y, b.z, b.w};
    int s = 0;
    #pragma unroll
    for (int j = 0; j < 8; j++) s += v[j];

    int x = s;                          // inclusive scan of thread sums
    #pragma unroll
    for (int d = 1; d < 32; d <<= 1) {
        int y = __shfl_up_sync(0xffffffffu, x, d);
        if (lane >= d) x += y;
    }
    if (lane == 31) wsum[w] = x;
    __syncthreads();
    if (t < 8) {                        // tiny serial-ish scan of 8 warp sums
        int ws = wsum[t];
        int p = 0;
        #pragma unroll
        for (int q = 0; q < 8; q++) {
            int val = __shfl_sync(0xffu, ws, q);
            if (q < t) p += val;
        }
        wsum[t] = p;                    // exclusive warp offsets
    }
    __syncthreads();

    int run = (x - s) + wsum[w];        // exclusive prefix for this thread
    int o[8];
    #pragma unroll
    for (int j = 0; j < 8; j++) { o[j] = run; run += v[j]; }
    *(int4*)(off + base)     = make_int4(o[0], o[1], o[2], o[3]);
    *(int4*)(off + base + 4) = make_int4(o[4], o[5], o[6], o[7]);
    if (t == 255) bsum[blockIdx.x] = run;   // block total
}

// Stage 2: exclusive scan of <=32 block totals (single warp).
__global__ void scan_bsums(int* __restrict__ bsum, int nb) {
    int lane = threadIdx.x;
    int v = (lane < nb) ? bsum[lane] : 0;
    int x = v;
    #pragma unroll
    for (int d = 1; d < 32; d <<= 1) {
        int y = __shfl_up_sync(0xffffffffu, x, d);
        if (lane >= d) x += y;
    }
    bsum[lane] = x - v;                 // exclusive (lanes >= nb get total)
}

__device__ __forceinline__ int off_of(const int* off, const int* bsum, int i) {
    return off[i] + bsum[i >> 11];
}

// Placement: pure scatter, no atomics.
__global__ void place_scatter(const int* __restrict__ row,
                              const int* __restrict__ col,
                              const int* __restrict__ slot,
                              const int* __restrict__ off,
                              const int* __restrict__ bsum,
                              int* __restrict__ eidx, int E) {
    int i = blockIdx.x * blockDim.x + threadIdx.x;
    if (i < E) {
        int c = col[i];
        eidx[off_of(off, bsum, c) + slot[i]] = row[i];
    }
}

// ---------------------------------------------------------------------
// Aggregation: one warp per destination row; gather + sum, write mean.
// ---------------------------------------------------------------------
__global__ void agg_kernel(const float* __restrict__ xsrc,
                           const int* __restrict__ off,
                           const int* __restrict__ bsum,
                           const int* __restrict__ eidx,
                           float* __restrict__ agg, int n) {
    int c    = (blockIdx.x * blockDim.x + threadIdx.x) >> 5;
    int lane = threadIdx.x & 31;
    if (c >= n) return;
    int s = off_of(off, bsum, c), e = off_of(off, bsum, c + 1);

    float4 acc = make_float4(0.f, 0.f, 0.f, 0.f);
    int i = s;
    for (; i + 4 <= e; i += 4) {
        int r0 = eidx[i + 0], r1 = eidx[i + 1];
        int r2 = eidx[i + 2], r3 = eidx[i + 3];
        float4 v0 = ((const float4*)(xsrc + (size_t)r0 * D))[lane];
        float4 v1 = ((const float4*)(xsrc + (size_t)r1 * D))[lane];
        float4 v2 = ((const float4*)(xsrc + (size_t)r2 * D))[lane];
        float4 v3 = ((const float4*)(xsrc + (size_t)r3 * D))[lane];
        acc.x += (v0.x + v1.x) + (v2.x + v3.x);
        acc.y += (v0.y + v1.y) + (v2.y + v3.y);
        acc.z += (v0.z + v1.z) + (v2.z + v3.z);
        acc.w += (v0.w + v1.w) + (v2.w + v3.w);
    }
    for (; i < e; i++) {
        int r = eidx[i];
        float4 v = ((const float4*)(xsrc + (size_t)r * D))[lane];
        acc.x += v.x; acc.y += v.y; acc.z += v.z; acc.w += v.w;
    }
    float invd = (e > s) ? 1.0f / (float)(e - s) : 0.f;
    acc.x *= invd; acc.y *= invd; acc.z *= invd; acc.w *= invd;
    ((float4*)(agg + (size_t)c * D))[lane] = acc;
}

// ---------------------------------------------------------------------
// SAGE finish with f32x2 FMA. ONE weight buffer in SMEM at a time ->
// ~101 KB smem -> 2 blocks/SM (16 warps/SM) for FMA-pipe saturation.
// ---------------------------------------------------------------------
#define KS 132
#define RPW 8
#define WARPS 8
#define ROWS_PER_BLOCK (RPW * WARPS)
#define SAGE_SMEM_BYTES ((KS * D + D + ROWS_PER_BLOCK * D) * 4)

__device__ __forceinline__ u64t pack2(float a) {
    u64t r;
    unsigned ai = __float_as_uint(a);
    asm("mov.b64 %0, {%1, %1};" : "=l"(r) : "r"(ai));
    return r;
}
__device__ __forceinline__ void ffma2(u64t& d, u64t a, u64t b) {
    asm("fma.rn.f32x2 %0, %1, %2, %3;" : "=l"(d) : "l"(a), "l"(b), "l"(d));
}

template <bool RELU>
__global__ void __launch_bounds__(256, 2)
sage_kernel(const float* __restrict__ agg,
            const float* __restrict__ xdst,
            const float* __restrict__ Wl, const float* __restrict__ bl,
            const float* __restrict__ Wr,
            float* __restrict__ out, int n) {
    extern __shared__ float smem[];
    float* sW  = smem;                    // KS * 128 (transposed, reused)
    float* sb  = smem + KS * D;           // 128
    float* sIn = sb + D;                  // 64 * 128 staging

    const int tid  = threadIdx.x;
    const int lane = tid & 31;
    const int warp = tid >> 5;
    const int l4   = lane * 4;

    // load Wl transposed + bias
    for (int idx = tid; idx < D * D; idx += 256) {
        int j = idx >> 7, k = idx & (D - 1);
        sW[k * KS + j] = Wl[idx];
    }
    if (tid < D) sb[tid] = bl[tid];

    float* myIn = sIn + warp * (RPW * D);
    const int rowBase = blockIdx.x * ROWS_PER_BLOCK + warp * RPW;

    // stage mean rows
    #pragma unroll
    for (int r = 0; r < RPW; r++) {
        int row = rowBase + r;
        float4 v = make_float4(0.f, 0.f, 0.f, 0.f);
        if (row < n) v = ((const float4*)(agg + (size_t)row * D))[lane];
        ((float4*)(myIn + r * D))[lane] = v;
    }
    __syncthreads();

    u64t acc[RPW][2];
    {
        u64t b0 = *(const u64t*)&sb[l4];
        u64t b1 = *(const u64t*)&sb[l4 + 2];
        #pragma unroll
        for (int r = 0; r < RPW; r++) { acc[r][0] = b0; acc[r][1] = b1; }
    }

    // ---- phase A: mean @ Wl^T ----
    #pragma unroll 4
    for (int k = 0; k < D; k++) {
        ulonglong2 w = *(const ulonglong2*)&sW[k * KS + l4];
        #pragma unroll
        for (int r = 0; r < RPW; r++) {
            u64t a = pack2(myIn[r * D + k]);
            ffma2(acc[r][0], a, w.x);
            ffma2(acc[r][1], a, w.y);
        }
    }
    __syncthreads();   // done reading Wl + mean staging

    // reload buffer with Wr; restage xdst
    for (int idx = tid; idx < D * D; idx += 256) {
        int j = idx >> 7, k = idx & (D - 1);
        sW[k * KS + j] = Wr[idx];
    }
    #pragma unroll
    for (int r = 0; r < RPW; r++) {
        int row = rowBase + r;
        float4 v = make_float4(0.f, 0.f, 0.f, 0.f);
        if (row < n) v = ((const float4*)(xdst + (size_t)row * D))[lane];
        ((float4*)(myIn + r * D))[lane] = v;
    }
    __syncthreads();

    // ---- phase B: + xdst @ Wr^T ----
    #pragma unroll 4
    for (int k = 0; k < D; k++) {
        ulonglong2 w = *(const ulonglong2*)&sW[k * KS + l4];
        #pragma unroll
        for (int r = 0; r < RPW; r++) {
            u64t a = pack2(myIn[r * D + k]);
            ffma2(acc[r][0], a, w.x);
            ffma2(acc[r][1], a, w.y);
        }
    }

    // ---- L2-normalize, (ReLU), store ----
    union F2 { u64t u; float2 f; };
    #pragma unroll
    for (int r = 0; r < RPW; r++) {
        int row = rowBase + r;
        F2 a0, a1; a0.u = acc[r][0]; a1.u = acc[r][1];
        float o0 = a0.f.x, o1 = a0.f.y, o2 = a1.f.x, o3 = a1.f.y;
        float s = o0 * o0 + o1 * o1 + o2 * o2 + o3 * o3;
        #pragma unroll
        for (int off = 16; off > 0; off >>= 1)
            s += __shfl_xor_sync(0xFFFFFFFFu, s, off);
        float inv = 1.0f / fmaxf(sqrtf(s), 1e-12f);
        o0 *= inv; o1 *= inv; o2 *= inv; o3 *= inv;
        if (RELU) {
            o0 = fmaxf(o0, 0.f); o1 = fmaxf(o1, 0.f);
            o2 = fmaxf(o2, 0.f); o3 = fmaxf(o3, 0.f);
        }
        if (row < n)
            ((float4*)(out + (size_t)row * D))[lane] = make_float4(o0, o1, o2, o3);
    }
}

// ---------------------------------------------------------------------
// Launch sequence. CSR2 build runs on a forked side stream (event
// fork/join) so it hides under the layer-1 critical path.
// ---------------------------------------------------------------------
extern "C" void kernel_launch(void* const* d_in, const int* in_sizes, int n_in,
                              void* d_out, int out_size) {
    const float* x    = (const float*)d_in[0];
    const float* Wl1  = (const float*)d_in[1];
    const float* bl1  = (const float*)d_in[2];
    const float* Wr1  = (const float*)d_in[3];
    const float* Wl2  = (const float*)d_in[4];
    const float* bl2  = (const float*)d_in[5];
    const float* Wr2  = (const float*)d_in[6];
    const int*   row1 = (const int*)d_in[7];
    const int*   col1 = (const int*)d_in[8];
    const int*   row2 = (const int*)d_in[9];
    const int*   col2 = (const int*)d_in[10];
    float* out = (float*)d_out;

    int *cnt1, *off1, *bsum1, *eidx1, *slot1;
    int *cnt2, *off2, *bsum2, *eidx2, *slot2;
    float *agg, *h;
    cudaGetSymbolAddress((void**)&cnt1, g_cnt1);
    cudaGetSymbolAddress((void**)&off1, g_off1);
    cudaGetSymbolAddress((void**)&bsum1, g_bsum1);
    cudaGetSymbolAddress((void**)&eidx1, g_eidx1);
    cudaGetSymbolAddress((void**)&slot1, g_slot1);
    cudaGetSymbolAddress((void**)&cnt2, g_cnt2);
    cudaGetSymbolAddress((void**)&off2, g_off2);
    cudaGetSymbolAddress((void**)&bsum2, g_bsum2);
    cudaGetSymbolAddress((void**)&eidx2, g_eidx2);
    cudaGetSymbolAddress((void**)&slot2, g_slot2);
    cudaGetSymbolAddress((void**)&agg, g_agg);
    cudaGetSymbolAddress((void**)&h,   g_h);

    cudaFuncSetAttribute(sage_kernel<true>,
                         cudaFuncAttributeMaxDynamicSharedMemorySize, SAGE_SMEM_BYTES);
    cudaFuncSetAttribute(sage_kernel<false>,
                         cudaFuncAttributeMaxDynamicSharedMemorySize, SAGE_SMEM_BYTES);

    // one-time side stream + fork/join events (host objects, no device mem)
    static cudaStream_t s_side = nullptr;
    static cudaEvent_t  s_ev0  = nullptr, s_ev1 = nullptr;
    if (!s_side) {
        cudaStreamCreateWithFlags(&s_side, cudaStreamNonBlocking);
        cudaEventCreateWithFlags(&s_ev0, cudaEventDisableTiming);
        cudaEventCreateWithFlags(&s_ev1, cudaEventDisableTiming);
    }

    // zero both count arrays (padded) in one kernel
    {
        int nmax = N_MID + SCAN_CHUNK;
        zero_all<<<(nmax + 255) / 256, 256>>>(cnt1, N_MID + SCAN_CHUNK,
                                              cnt2, N_DST + SCAN_CHUNK);
    }

    // ---- fork: CSR2 build on side stream ----
    cudaEventRecord(s_ev0, 0);
    cudaStreamWaitEvent(s_side, s_ev0, 0);
    hist_slot<<<(E2 + 255) / 256, 256, 0, s_side>>>(col2, cnt2, slot2, E2);
    scan_partial<<<NB2, 256, 0, s_side>>>(cnt2, off2, bsum2);
    scan_bsums<<<1, 32, 0, s_side>>>(bsum2, NB2);
    place_scatter<<<(E2 + 255) / 256, 256, 0, s_side>>>(row2, col2, slot2,
                                                        off2, bsum2, eidx2, E2);
    cudaEventRecord(s_ev1, s_side);

    // ---- main: CSR1 build + layer 1 ----
    hist_slot<<<(E1 + 255) / 256, 256>>>(col1, cnt1, slot1, E1);
    scan_partial<<<NB1, 256>>>(cnt1, off1, bsum1);
    scan_bsums<<<1, 32>>>(bsum1, NB1);
    place_scatter<<<(E1 + 255) / 256, 256>>>(row1, col1, slot1,
                                             off1, bsum1, eidx1, E1);
    agg_kernel<<<(N_MID * 32 + 255) / 256, 256>>>(x, off1, bsum1, eidx1,
                                                  agg, N_MID);
    sage_kernel<true><<<(N_MID + ROWS_PER_BLOCK - 1) / ROWS_PER_BLOCK, 256,
                        SAGE_SMEM_BYTES>>>(agg, x, Wl1, bl1, Wr1, h, N_MID);

    // ---- join, then layer 2 ----
    cudaStreamWaitEvent(0, s_ev1, 0);
    agg_kernel<<<(N_DST * 32 + 255) / 256, 256>>>(h, off2, bsum2, eidx2,
                                                  agg, N_DST);
    sage_kernel<false><<<(N_DST + ROWS_PER_BLOCK - 1) / ROWS_PER_BLOCK, 256,
                         SAGE_SMEM_BYTES>>>(agg, h, Wl2, bl2, Wr2, out, N_DST);
}